// round 1
// baseline (speedup 1.0000x reference)
#include <cuda_runtime.h>
#include <math.h>

// ---------------------------------------------------------------------------
// Problem constants
// ---------------------------------------------------------------------------
#define SEQ_LEN   8
#define D_MODEL   2048
#define OUT_DIM   1152
#define WAY       5
#define SHOT      5
#define N_SUPPORT 25
#define N_QUERIES 200
#define N_TOTAL   225           // N_SUPPORT + N_QUERIES
#define L_TUP     28
#define TWO_D     4096
#define NSTACK    4608          // 4 * OUT_DIM  (k half0, k half1, v half0, v half1)
#define ROWS_X    1800          // N_TOTAL * SEQ_LEN
#define ROWS_Q    5600          // N_QUERIES * L_TUP
#define ROWS_S    700           // N_SUPPORT * L_TUP
#define SEG       140           // SHOT * L_TUP
#define PLANE     32256         // L_TUP * OUT_DIM

__constant__ int c_t0[L_TUP] = {0,0,0,0,0,0,0,1,1,1,1,1,1,2,2,2,2,2,3,3,3,3,4,4,4,5,5,6};
__constant__ int c_t1[L_TUP] = {1,2,3,4,5,6,7,2,3,4,5,6,7,3,4,5,6,7,4,5,6,7,5,6,7,6,7,7};

// ---------------------------------------------------------------------------
// Scratch (device globals; no allocation allowed)
// ---------------------------------------------------------------------------
__device__ float g_X[ROWS_X * D_MODEL];            // inputs + positional encoding
__device__ float g_Wt[NSTACK * D_MODEL];           // stacked weights, [N,K] row-major
__device__ float g_P[ROWS_X * NSTACK];             // per-position partial projections
__device__ float g_ks_s[ROWS_S * OUT_DIM];
__device__ float g_ks_q[ROWS_Q * OUT_DIM];
__device__ float g_vs_s[ROWS_S * OUT_DIM];
__device__ float g_vs_q[ROWS_Q * OUT_DIM];
__device__ float g_S[ROWS_Q * ROWS_S];             // scores -> attn (in place)
__device__ float g_proto[WAY * ROWS_Q * OUT_DIM];  // [w][q*28+l][d]

// ---------------------------------------------------------------------------
// Kernel 1: X = [support; queries] + positional encoding
// ---------------------------------------------------------------------------
__global__ void add_pe_kernel(const float* __restrict__ support,
                              const float* __restrict__ queries)
{
    int e = blockIdx.x * blockDim.x + threadIdx.x;
    const int total = ROWS_X * D_MODEL;
    if (e >= total) return;
    int n   = e / (SEQ_LEN * D_MODEL);
    int rem = e % (SEQ_LEN * D_MODEL);
    int s   = rem / D_MODEL;
    int d   = rem % D_MODEL;

    const float c = -9.210340371976184f / (float)D_MODEL;   // -ln(10000)/D
    float div = expf((float)(2 * (d >> 1)) * c);
    float arg = (float)s * div;
    float pe = ((d & 1) ? cosf(arg) : sinf(arg)) * 0.1f;

    float x = (n < N_SUPPORT) ? support[e]
                              : queries[e - N_SUPPORT * SEQ_LEN * D_MODEL];
    g_X[e] = x + pe;
}

// ---------------------------------------------------------------------------
// Kernel 2: build stacked weight matrix Wt [NSTACK, D_MODEL] row-major
//   col-block 0: k_w[:, 0:2048]  1: k_w[:, 2048:]  2: v_w[:, 0:2048]  3: v_w[:, 2048:]
// ---------------------------------------------------------------------------
__global__ void build_wt_kernel(const float* __restrict__ k_w,
                                const float* __restrict__ v_w)
{
    int e = blockIdx.x * blockDim.x + threadIdx.x;
    const int total = NSTACK * D_MODEL;
    if (e >= total) return;
    int j = e / D_MODEL;
    int k = e % D_MODEL;
    int part = j / OUT_DIM;          // 0..3
    int o    = j % OUT_DIM;
    const float* w = (part < 2) ? k_w : v_w;
    g_Wt[e] = w[(size_t)o * TWO_D + (part & 1) * D_MODEL + k];
}

// ---------------------------------------------------------------------------
// Tiled fp32 GEMM.  C[M,N] = alpha * A[M,K] * op(B)
//   TRANSB = true : B stored [N,K] row-major (C = A * B^T)
//   TRANSB = false: B stored [K,N] row-major (C = A * B)
// 128x128 block tile, BK=8, 8x8 per thread, 256 threads. Full bounds checks.
// ---------------------------------------------------------------------------
#define BM 128
#define BN 128
#define BK 8
#define TM 8
#define TN 8

template<bool TRANSB>
__global__ __launch_bounds__(256)
void sgemm_kernel(const float* __restrict__ A, const float* __restrict__ B,
                  float* __restrict__ C, int M, int N, int K,
                  int lda, int ldb, int ldc, float alpha)
{
    __shared__ float As[BK][BM];
    __shared__ float Bs[BK][BN];

    const int tid  = threadIdx.x;
    const int row0 = blockIdx.y * BM;
    const int col0 = blockIdx.x * BN;

    const int tRow = (tid / 16) * TM;
    const int tCol = (tid % 16) * TN;

    float acc[TM][TN];
    #pragma unroll
    for (int i = 0; i < TM; i++)
        #pragma unroll
        for (int j = 0; j < TN; j++) acc[i][j] = 0.f;

    const int aRow = tid >> 1;           // 0..127
    const int aK0  = (tid & 1) * 4;      // 0 or 4

    for (int k0 = 0; k0 < K; k0 += BK) {
        // ---- load A tile (transposed into As[k][m]) ----
        {
            int r = row0 + aRow;
            #pragma unroll
            for (int i = 0; i < 4; i++) {
                int k = aK0 + i;
                float v = 0.f;
                if (r < M && (k0 + k) < K) v = A[(size_t)r * lda + k0 + k];
                As[k][aRow] = v;
            }
        }
        // ---- load B tile ----
        if (TRANSB) {
            int j = tid >> 1;
            int c = col0 + j;
            #pragma unroll
            for (int i = 0; i < 4; i++) {
                int k = (tid & 1) * 4 + i;
                float v = 0.f;
                if (c < N && (k0 + k) < K) v = B[(size_t)c * ldb + k0 + k];
                Bs[k][j] = v;
            }
        } else {
            int k = tid >> 5;            // 0..7
            #pragma unroll
            for (int i = 0; i < 4; i++) {
                int j = (tid & 31) * 4 + i;
                int c = col0 + j;
                float v = 0.f;
                if (c < N && (k0 + k) < K) v = B[(size_t)(k0 + k) * ldb + c];
                Bs[k][j] = v;
            }
        }
        __syncthreads();

        #pragma unroll
        for (int k = 0; k < BK; k++) {
            float rm[TM], rn[TN];
            #pragma unroll
            for (int i = 0; i < TM; i++) rm[i] = As[k][tRow + i];
            #pragma unroll
            for (int j = 0; j < TN; j++) rn[j] = Bs[k][tCol + j];
            #pragma unroll
            for (int i = 0; i < TM; i++)
                #pragma unroll
                for (int j = 0; j < TN; j++)
                    acc[i][j] += rm[i] * rn[j];
        }
        __syncthreads();
    }

    #pragma unroll
    for (int i = 0; i < TM; i++) {
        int r = row0 + tRow + i;
        if (r >= M) continue;
        #pragma unroll
        for (int j = 0; j < TN; j++) {
            int c = col0 + tCol + j;
            if (c < N) C[(size_t)r * ldc + c] = alpha * acc[i][j];
        }
    }
}

// ---------------------------------------------------------------------------
// Kernel 4: assemble tuple features + LayerNorm(k), plain v.
// One block per (n, l) row.
// ---------------------------------------------------------------------------
__global__ __launch_bounds__(256)
void assemble_kernel(const float* __restrict__ k_b, const float* __restrict__ v_b,
                     const float* __restrict__ ln_g, const float* __restrict__ ln_b)
{
    int rl = blockIdx.x;                 // 0 .. N_TOTAL*L_TUP-1
    int n  = rl / L_TUP;
    int l  = rl % L_TUP;
    int t0 = c_t0[l], t1 = c_t1[l];
    const float* P0 = g_P + (size_t)(n * SEQ_LEN + t0) * NSTACK;
    const float* P1 = g_P + (size_t)(n * SEQ_LEN + t1) * NSTACK;

    float *ksd, *vsd;
    if (n < N_SUPPORT) {
        ksd = g_ks_s + (size_t)(n * L_TUP + l) * OUT_DIM;
        vsd = g_vs_s + (size_t)(n * L_TUP + l) * OUT_DIM;
    } else {
        int m = n - N_SUPPORT;
        ksd = g_ks_q + (size_t)(m * L_TUP + l) * OUT_DIM;
        vsd = g_vs_q + (size_t)(m * L_TUP + l) * OUT_DIM;
    }

    __shared__ float kbuf[OUT_DIM];
    float s = 0.f, s2 = 0.f;
    for (int o = threadIdx.x; o < OUT_DIM; o += blockDim.x) {
        float kv = P0[o] + P1[OUT_DIM + o] + k_b[o];
        kbuf[o] = kv;
        s  += kv;
        s2 += kv * kv;
        float vv = P0[2 * OUT_DIM + o] + P1[3 * OUT_DIM + o] + v_b[o];
        vsd[o] = vv;
    }
    // block reduce (s, s2)
    int lane = threadIdx.x & 31, wid = threadIdx.x >> 5;
    #pragma unroll
    for (int off = 16; off; off >>= 1) {
        s  += __shfl_xor_sync(0xffffffffu, s,  off);
        s2 += __shfl_xor_sync(0xffffffffu, s2, off);
    }
    __shared__ float ws[8], ws2[8];
    __shared__ float sm_mean, sm_rstd;
    if (lane == 0) { ws[wid] = s; ws2[wid] = s2; }
    __syncthreads();
    if (threadIdx.x == 0) {
        float S = 0.f, S2 = 0.f;
        #pragma unroll
        for (int w = 0; w < 8; w++) { S += ws[w]; S2 += ws2[w]; }
        float mean = S / (float)OUT_DIM;
        float var  = S2 / (float)OUT_DIM - mean * mean;
        sm_mean = mean;
        sm_rstd = rsqrtf(var + 1e-5f);
    }
    __syncthreads();
    float mean = sm_mean, rstd = sm_rstd;
    for (int o = threadIdx.x; o < OUT_DIM; o += blockDim.x)
        ksd[o] = (kbuf[o] - mean) * rstd * ln_g[o] + ln_b[o];
}

// ---------------------------------------------------------------------------
// Kernel 6: per-row blockwise softmax. One block per (q,l) row; warp w handles
// the 140-column segment of class w.
// ---------------------------------------------------------------------------
__global__ __launch_bounds__(160)
void softmax_kernel()
{
    int row  = blockIdx.x;               // 0..5599
    int warp = threadIdx.x >> 5;         // 0..4  (class)
    int lane = threadIdx.x & 31;
    float* p = g_S + (size_t)row * ROWS_S + warp * SEG;

    float v[5];
    float mx = -INFINITY;
    #pragma unroll
    for (int i = 0; i < 5; i++) {
        int c = lane + 32 * i;
        v[i] = (c < SEG) ? p[c] : -INFINITY;
        mx = fmaxf(mx, v[i]);
    }
    #pragma unroll
    for (int off = 16; off; off >>= 1)
        mx = fmaxf(mx, __shfl_xor_sync(0xffffffffu, mx, off));
    float sm = 0.f;
    #pragma unroll
    for (int i = 0; i < 5; i++) {
        int c = lane + 32 * i;
        v[i] = (c < SEG) ? expf(v[i] - mx) : 0.f;
        sm += v[i];
    }
    #pragma unroll
    for (int off = 16; off; off >>= 1)
        sm += __shfl_xor_sync(0xffffffffu, sm, off);
    float inv = 1.f / sm;
    #pragma unroll
    for (int i = 0; i < 5; i++) {
        int c = lane + 32 * i;
        if (c < SEG) p[c] = v[i] * inv;
    }
}

// ---------------------------------------------------------------------------
// Kernel 8: per-query Gram matrix + distances -> sim, ori.
// One block (256 threads) per query.
// ---------------------------------------------------------------------------
__global__ __launch_bounds__(256)
void finalize_kernel(float* __restrict__ out)
{
    int q = blockIdx.x;
    const float* v = g_vs_q + (size_t)q * PLANE;
    const float* pp[WAY];
    #pragma unroll
    for (int w = 0; w < WAY; w++)
        pp[w] = g_proto + (size_t)w * ROWS_Q * OUT_DIM + (size_t)q * PLANE;

    // 21 accumulators: G upper-tri (15), dot(v, p_w) (5), ||v||^2 (1)
    float acc[21];
    #pragma unroll
    for (int i = 0; i < 21; i++) acc[i] = 0.f;

    for (int i = threadIdx.x; i < PLANE; i += blockDim.x) {
        float vv = v[i];
        float a0 = pp[0][i], a1 = pp[1][i], a2 = pp[2][i], a3 = pp[3][i], a4 = pp[4][i];
        acc[0]  += a0 * a0;  acc[1]  += a0 * a1;  acc[2]  += a0 * a2;
        acc[3]  += a0 * a3;  acc[4]  += a0 * a4;
        acc[5]  += a1 * a1;  acc[6]  += a1 * a2;  acc[7]  += a1 * a3;  acc[8]  += a1 * a4;
        acc[9]  += a2 * a2;  acc[10] += a2 * a3;  acc[11] += a2 * a4;
        acc[12] += a3 * a3;  acc[13] += a3 * a4;
        acc[14] += a4 * a4;
        acc[15] += vv * a0;  acc[16] += vv * a1;  acc[17] += vv * a2;
        acc[18] += vv * a3;  acc[19] += vv * a4;
        acc[20] += vv * vv;
    }

    int lane = threadIdx.x & 31, wid = threadIdx.x >> 5;
    __shared__ float part[21][8];
    #pragma unroll
    for (int i = 0; i < 21; i++) {
        float a = acc[i];
        #pragma unroll
        for (int off = 16; off; off >>= 1)
            a += __shfl_xor_sync(0xffffffffu, a, off);
        if (lane == 0) part[i][wid] = a;
    }
    __syncthreads();
    __shared__ float tot[21];
    if (threadIdx.x < 21) {
        float sSum = 0.f;
        #pragma unroll
        for (int w = 0; w < 8; w++) sSum += part[threadIdx.x][w];
        tot[threadIdx.x] = sSum;
    }
    __syncthreads();
    if (threadIdx.x == 0) {
        float G[WAY][WAY];
        int t = 0;
        for (int a = 0; a < WAY; a++)
            for (int b = a; b < WAY; b++) { G[a][b] = tot[t]; G[b][a] = tot[t]; t++; }
        float D[WAY];
        for (int w = 0; w < WAY; w++) D[w] = tot[15 + w];
        float VV = tot[20];
        float nrm[WAY];
        for (int w = 0; w < WAY; w++) nrm[w] = sqrtf(G[w][w]);
        // sim: [Nq, WAY, WAY]
        for (int a = 0; a < WAY; a++)
            for (int b = 0; b < WAY; b++)
                out[q * WAY * WAY + a * WAY + b] =
                    G[a][b] / fmaxf(nrm[a] * nrm[b], 1e-8f);
        // ori: [Nq, WAY] at offset Nq*WAY*WAY
        for (int w = 0; w < WAY; w++)
            out[N_QUERIES * WAY * WAY + q * WAY + w] =
                -(VV - 2.f * D[w] + G[w][w]) / (float)L_TUP;
    }
}

// ---------------------------------------------------------------------------
// Launch
// ---------------------------------------------------------------------------
extern "C" void kernel_launch(void* const* d_in, const int* in_sizes, int n_in,
                              void* d_out, int out_size)
{
    const float* support = (const float*)d_in[0];
    // d_in[1]: support_labels (unused; sorted equal-shot episode)
    const float* queries = (const float*)d_in[2];
    const float* k_w  = (const float*)d_in[3];
    const float* k_b  = (const float*)d_in[4];
    const float* v_w  = (const float*)d_in[5];
    const float* v_b  = (const float*)d_in[6];
    const float* ln_g = (const float*)d_in[7];
    const float* ln_b = (const float*)d_in[8];
    float* out = (float*)d_out;

    float *X, *Wt, *P, *kss, *ksq, *vss, *vsq, *S, *proto;
    cudaGetSymbolAddress((void**)&X,     g_X);
    cudaGetSymbolAddress((void**)&Wt,    g_Wt);
    cudaGetSymbolAddress((void**)&P,     g_P);
    cudaGetSymbolAddress((void**)&kss,   g_ks_s);
    cudaGetSymbolAddress((void**)&ksq,   g_ks_q);
    cudaGetSymbolAddress((void**)&vss,   g_vs_s);
    cudaGetSymbolAddress((void**)&vsq,   g_vs_q);
    cudaGetSymbolAddress((void**)&S,     g_S);
    cudaGetSymbolAddress((void**)&proto, g_proto);

    // 1. X = inputs + positional encoding
    {
        int total = ROWS_X * D_MODEL;
        add_pe_kernel<<<(total + 255) / 256, 256>>>(support, queries);
    }
    // 2. stacked weights
    {
        int total = NSTACK * D_MODEL;
        build_wt_kernel<<<(total + 255) / 256, 256>>>(k_w, v_w);
    }
    // 3. P = X @ Wt^T   [1800, 4608]
    {
        dim3 grid((NSTACK + BN - 1) / BN, (ROWS_X + BM - 1) / BM);
        sgemm_kernel<true><<<grid, 256>>>(X, Wt, P, ROWS_X, NSTACK, D_MODEL,
                                          D_MODEL, D_MODEL, NSTACK, 1.0f);
    }
    // 4. assemble ks (LayerNorm) / vs
    assemble_kernel<<<N_TOTAL * L_TUP, 256>>>(k_b, v_b, ln_g, ln_b);

    // 5. scores = ks_q @ ks_s^T / sqrt(OUT_DIM)   [5600, 700]
    {
        dim3 grid((ROWS_S + BN - 1) / BN, (ROWS_Q + BM - 1) / BM);
        sgemm_kernel<true><<<grid, 256>>>(ksq, kss, S, ROWS_Q, ROWS_S, OUT_DIM,
                                          OUT_DIM, OUT_DIM, ROWS_S,
                                          1.0f / sqrtf((float)OUT_DIM));
    }
    // 6. blockwise softmax (in place on S)
    softmax_kernel<<<ROWS_Q, 160>>>();

    // 7. proto[w] = attn[:, w*140:(w+1)*140] @ vs_s[w*140:(w+1)*140, :]
    {
        dim3 grid((OUT_DIM + BN - 1) / BN, (ROWS_Q + BM - 1) / BM);
        for (int w = 0; w < WAY; w++) {
            sgemm_kernel<false><<<grid, 256>>>(
                S + w * SEG, vss + (size_t)w * SEG * OUT_DIM,
                proto + (size_t)w * ROWS_Q * OUT_DIM,
                ROWS_Q, OUT_DIM, SEG, ROWS_S, OUT_DIM, OUT_DIM, 1.0f);
        }
    }
    // 8. per-query Gram + distances -> sim, ori
    finalize_kernel<<<N_QUERIES, 256>>>(out);
}

// round 3
// speedup vs baseline: 4.0498x; 4.0498x over previous
#include <cuda_runtime.h>
#include <cuda_bf16.h>
#include <math.h>
#include <stdint.h>

// ---------------------------------------------------------------------------
// Problem constants
// ---------------------------------------------------------------------------
#define SEQ_LEN   8
#define D_MODEL   2048
#define OUT_DIM   1152
#define WAY       5
#define SHOT      5
#define N_SUPPORT 25
#define N_QUERIES 200
#define N_TOTAL   225
#define L_TUP     28
#define TWO_D     4096
#define NSTACK    4608          // 4 * OUT_DIM (k h0, k h1, v h0, v h1)
#define ROWS_X    1800          // N_TOTAL * SEQ_LEN
#define ROWS_Q    5600          // N_QUERIES * L_TUP
#define ROWS_S    700           // N_SUPPORT * L_TUP
#define SEG       140           // SHOT * L_TUP
#define PLANE     32256         // L_TUP * OUT_DIM

// hi/lo-split K sizes (3x, multiple of 32)
#define KBIG      6144          // 3 * 2048
#define KSC       3456          // 3 * 1152
#define KPR       448           // 3 * 140 = 420, padded to 448

__constant__ int c_t0[L_TUP] = {0,0,0,0,0,0,0,1,1,1,1,1,1,2,2,2,2,2,3,3,3,3,4,4,4,5,5,6};
__constant__ int c_t1[L_TUP] = {1,2,3,4,5,6,7,2,3,4,5,6,7,3,4,5,6,7,4,5,6,7,5,6,7,6,7,7};

// ---------------------------------------------------------------------------
// Scratch (device globals; no allocation allowed)
// ---------------------------------------------------------------------------
__device__ float          g_X[ROWS_X * D_MODEL];
__device__ __nv_bfloat16  g_Xhl[(size_t)ROWS_X * KBIG];     // A-layout (hi,hi,lo)
__device__ __nv_bfloat16  g_Whl[(size_t)NSTACK * KBIG];     // B-layout (hi,lo,hi)
__device__ float          g_P[(size_t)ROWS_X * NSTACK];
__device__ float          g_ks_s[ROWS_S * OUT_DIM];
__device__ float          g_ks_q[ROWS_Q * OUT_DIM];
__device__ float          g_vs_s[ROWS_S * OUT_DIM];
__device__ float          g_vs_q[ROWS_Q * OUT_DIM];
__device__ __nv_bfloat16  g_KQhl[(size_t)ROWS_Q * KSC];     // A-layout
__device__ __nv_bfloat16  g_KShl[(size_t)ROWS_S * KSC];     // B-layout
__device__ float          g_S[(size_t)ROWS_Q * ROWS_S];     // scores -> attn in place
__device__ __nv_bfloat16  g_Ahl[(size_t)WAY * ROWS_Q * KPR];   // attn slices, A-layout
__device__ __nv_bfloat16  g_Vhl[(size_t)WAY * OUT_DIM * KPR];  // vs_s^T slices, B-layout
__device__ float          g_proto[(size_t)WAY * ROWS_Q * OUT_DIM];

// ---------------------------------------------------------------------------
// Helpers
// ---------------------------------------------------------------------------
__device__ __forceinline__ uint32_t smem_u32(const void* p) {
    uint32_t a;
    asm("{ .reg .u64 t; cvta.to.shared.u64 t, %1; cvt.u32.u64 %0, t; }"
        : "=r"(a) : "l"(p));
    return a;
}

#define CP16(dst, src) \
    asm volatile("cp.async.cg.shared.global [%0], [%1], 16;" :: "r"(dst), "l"(src))
#define CP_COMMIT() asm volatile("cp.async.commit_group;" ::: "memory")
#define CP_WAIT(n)  asm volatile("cp.async.wait_group %0;" :: "n"(n) : "memory")

// ---------------------------------------------------------------------------
// mma.sync bf16 GEMM: C[M,N] = alpha * A[M,K] * B[N,K]^T   (A,B K-major bf16)
// 128x128 CTA tile, BK=32, 3-stage cp.async pipeline, 8 warps (2x4), warp
// tile 64x32 via m16n8k16. K must be a multiple of 32. OOB rows clamped
// (their results feed only unstored outputs).
// ---------------------------------------------------------------------------
__global__ __launch_bounds__(256, 1)
void gemm_mma(const __nv_bfloat16* __restrict__ A, const __nv_bfloat16* __restrict__ B,
              float* __restrict__ C, int M, int N, int K, float alpha)
{
    __shared__ uint4 sbuf[3][1024];    // per stage: [0..511]=A (8KB), [512..1023]=B

    const int tid  = threadIdx.x;
    const int lane = tid & 31;
    const int wid  = tid >> 5;
    const int wm   = wid >> 2;         // 0..1  (warp row)
    const int wn   = wid & 3;          // 0..3  (warp col)
    const int row0 = blockIdx.y * 128;
    const int col0 = blockIdx.x * 128;

    // loader mapping: thread handles A chunks {tid, tid+256}, B chunks {tid, tid+256}
    // chunk ch (0..511): row = ch>>2, cq = ch&3 (16B column chunk)
    int l_sw[2];
    const __nv_bfloat16 *gA[2], *gB[2];
    #pragma unroll
    for (int i = 0; i < 2; i++) {
        int ch  = tid + i * 256;
        int row = ch >> 2, cq = ch & 3;
        l_sw[i] = row * 4 + ((cq ^ (row >> 1)) & 3);
        int ra = row0 + row; if (ra > M - 1) ra = M - 1;
        int rb = col0 + row; if (rb > N - 1) rb = N - 1;
        gA[i] = A + (size_t)ra * K + cq * 8;
        gB[i] = B + (size_t)rb * K + cq * 8;
    }

    const int NC = K >> 5;

    auto issue = [&](int stage, int c) {
        uint32_t base = smem_u32(&sbuf[stage][0]);
        #pragma unroll
        for (int i = 0; i < 2; i++) {
            CP16(base +        l_sw[i] * 16, gA[i] + c * 32);
            CP16(base + 8192 + l_sw[i] * 16, gB[i] + c * 32);
        }
        CP_COMMIT();
    };

    float acc[4][4][4];
    #pragma unroll
    for (int mi = 0; mi < 4; mi++)
        #pragma unroll
        for (int ni = 0; ni < 4; ni++)
            #pragma unroll
            for (int e = 0; e < 4; e++) acc[mi][ni][e] = 0.f;

    const int q = lane >> 3;           // 0..3 (ldmatrix quad)
    const int r = lane & 7;

    auto compute = [&](int stage) {
        uint32_t abase = smem_u32(&sbuf[stage][0]);
        uint32_t bbase = abase + 8192;
        #pragma unroll
        for (int ks = 0; ks < 2; ks++) {
            uint32_t af[4][4];
            #pragma unroll
            for (int mi = 0; mi < 4; mi++) {
                int row = wm * 64 + mi * 16 + r + (q & 1) * 8;
                int cq  = ks * 2 + (q >> 1);
                uint32_t ad = abase + (uint32_t)(row * 4 + ((cq ^ (row >> 1)) & 3)) * 16u;
                asm volatile("ldmatrix.sync.aligned.m8n8.x4.shared.b16 {%0,%1,%2,%3}, [%4];"
                    : "=r"(af[mi][0]), "=r"(af[mi][1]), "=r"(af[mi][2]), "=r"(af[mi][3])
                    : "r"(ad));
            }
            uint32_t bf[4][2];
            #pragma unroll
            for (int nh = 0; nh < 2; nh++) {
                int ni  = nh * 2 + (q >> 1);
                int row = wn * 32 + ni * 8 + r;
                int cq  = ks * 2 + (q & 1);
                uint32_t bd = bbase + (uint32_t)(row * 4 + ((cq ^ (row >> 1)) & 3)) * 16u;
                asm volatile("ldmatrix.sync.aligned.m8n8.x4.shared.b16 {%0,%1,%2,%3}, [%4];"
                    : "=r"(bf[nh*2][0]), "=r"(bf[nh*2][1]),
                      "=r"(bf[nh*2+1][0]), "=r"(bf[nh*2+1][1])
                    : "r"(bd));
            }
            #pragma unroll
            for (int mi = 0; mi < 4; mi++)
                #pragma unroll
                for (int ni = 0; ni < 4; ni++) {
                    asm volatile(
                        "mma.sync.aligned.m16n8k16.row.col.f32.bf16.bf16.f32 "
                        "{%0,%1,%2,%3}, {%4,%5,%6,%7}, {%8,%9}, {%0,%1,%2,%3};"
                        : "+f"(acc[mi][ni][0]), "+f"(acc[mi][ni][1]),
                          "+f"(acc[mi][ni][2]), "+f"(acc[mi][ni][3])
                        : "r"(af[mi][0]), "r"(af[mi][1]), "r"(af[mi][2]), "r"(af[mi][3]),
                          "r"(bf[ni][0]), "r"(bf[ni][1]));
                }
        }
    };

    // 3-stage pipeline
    issue(0, 0);
    if (NC > 1) issue(1, 1);
    for (int c = 0; c < NC; c++) {
        if (c + 2 < NC) issue((c + 2) % 3, c + 2);
        int rem = NC - 1 - c;
        if (rem >= 2)      CP_WAIT(2);
        else if (rem == 1) CP_WAIT(1);
        else               CP_WAIT(0);
        __syncthreads();
        compute(c % 3);
        __syncthreads();
    }

    // epilogue: float2 stores
    const int g  = lane >> 2;
    const int tg = lane & 3;
    #pragma unroll
    for (int mi = 0; mi < 4; mi++) {
        int rr0 = row0 + wm * 64 + mi * 16 + g;
        int rr1 = rr0 + 8;
        #pragma unroll
        for (int ni = 0; ni < 4; ni++) {
            int cc = col0 + wn * 32 + ni * 8 + tg * 2;
            if (cc < N) {
                if (rr0 < M) {
                    float2 v = make_float2(alpha * acc[mi][ni][0], alpha * acc[mi][ni][1]);
                    *(float2*)(C + (size_t)rr0 * N + cc) = v;
                }
                if (rr1 < M) {
                    float2 v = make_float2(alpha * acc[mi][ni][2], alpha * acc[mi][ni][3]);
                    *(float2*)(C + (size_t)rr1 * N + cc) = v;
                }
            }
        }
    }
}

// ---------------------------------------------------------------------------
// hi/lo split helpers
// ---------------------------------------------------------------------------
__device__ __forceinline__ void split2(float x, __nv_bfloat16& hi, __nv_bfloat16& lo) {
    hi = __float2bfloat16(x);
    lo = __float2bfloat16(x - __bfloat162float(hi));
}

// ORDER 0: A-layout (hi, hi, lo);  ORDER 1: B-layout (hi, lo, hi)
template<int ORDER>
__global__ void conv_hilo(const float* __restrict__ in, __nv_bfloat16* __restrict__ out,
                          int R, int Kin)
{
    int e = blockIdx.x * blockDim.x + threadIdx.x;
    if (e >= R * Kin) return;
    int r = e / Kin, k = e % Kin;
    __nv_bfloat16 hi, lo; split2(in[e], hi, lo);
    __nv_bfloat16* o = out + (size_t)r * (3 * Kin);
    o[k] = hi;
    o[Kin + k]     = (ORDER == 0) ? hi : lo;
    o[2 * Kin + k] = (ORDER == 0) ? lo : hi;
}

// stacked weights -> B-layout hi/lo
__global__ void convW_kernel(const float* __restrict__ k_w, const float* __restrict__ v_w)
{
    int e = blockIdx.x * blockDim.x + threadIdx.x;
    if (e >= NSTACK * D_MODEL) return;
    int j = e / D_MODEL, k = e % D_MODEL;
    int part = j / OUT_DIM, o = j % OUT_DIM;
    const float* w = (part < 2) ? k_w : v_w;
    float x = w[(size_t)o * TWO_D + (part & 1) * D_MODEL + k];
    __nv_bfloat16 hi, lo; split2(x, hi, lo);
    __nv_bfloat16* dst = g_Whl + (size_t)j * KBIG;
    dst[k] = hi; dst[D_MODEL + k] = lo; dst[2 * D_MODEL + k] = hi;
}

// attn slices -> A-layout [WAY][ROWS_Q][KPR] (hi, hi, lo), pad to 448 with 0
__global__ void conv_attn_kernel()
{
    int e = blockIdx.x * blockDim.x + threadIdx.x;
    const int total = WAY * ROWS_Q * KPR;
    if (e >= total) return;
    int w = e / (ROWS_Q * KPR);
    int rem = e % (ROWS_Q * KPR);
    int r = rem / KPR, j = rem % KPR;
    __nv_bfloat16 v = __float2bfloat16(0.f);
    if (j < 420) {
        int seg = j / SEG, jj = j - seg * SEG;
        float x = g_S[(size_t)r * ROWS_S + w * SEG + jj];
        __nv_bfloat16 hi, lo; split2(x, hi, lo);
        v = (seg == 2) ? lo : hi;
    }
    g_Ahl[e] = v;
}

// vs_s^T slices -> B-layout [WAY][OUT_DIM][KPR] (hi, lo, hi)
__global__ void conv_vsT_kernel()
{
    int e = blockIdx.x * blockDim.x + threadIdx.x;
    const int total = WAY * OUT_DIM * KPR;
    if (e >= total) return;
    int w = e / (OUT_DIM * KPR);
    int rem = e % (OUT_DIM * KPR);
    int d = rem / KPR, j = rem % KPR;
    __nv_bfloat16 v = __float2bfloat16(0.f);
    if (j < 420) {
        int seg = j / SEG, jj = j - seg * SEG;
        float x = g_vs_s[(size_t)(w * SEG + jj) * OUT_DIM + d];
        __nv_bfloat16 hi, lo; split2(x, hi, lo);
        v = (seg == 1) ? lo : hi;
    }
    g_Vhl[e] = v;
}

// ---------------------------------------------------------------------------
// X = [support; queries] + positional encoding
// ---------------------------------------------------------------------------
__global__ void add_pe_kernel(const float* __restrict__ support,
                              const float* __restrict__ queries)
{
    int e = blockIdx.x * blockDim.x + threadIdx.x;
    if (e >= ROWS_X * D_MODEL) return;
    int n = e / (SEQ_LEN * D_MODEL);
    int rem = e % (SEQ_LEN * D_MODEL);
    int s = rem / D_MODEL, d = rem % D_MODEL;
    const float c = -9.210340371976184f / (float)D_MODEL;
    float div = expf((float)(2 * (d >> 1)) * c);
    float arg = (float)s * div;
    float pe = ((d & 1) ? cosf(arg) : sinf(arg)) * 0.1f;
    float x = (n < N_SUPPORT) ? support[e]
                              : queries[e - N_SUPPORT * SEQ_LEN * D_MODEL];
    g_X[e] = x + pe;
}

// ---------------------------------------------------------------------------
// assemble tuple features + LayerNorm(k), plain v
// ---------------------------------------------------------------------------
__global__ __launch_bounds__(256)
void assemble_kernel(const float* __restrict__ k_b, const float* __restrict__ v_b,
                     const float* __restrict__ ln_g, const float* __restrict__ ln_b)
{
    int rl = blockIdx.x;
    int n = rl / L_TUP, l = rl % L_TUP;
    int t0 = c_t0[l], t1 = c_t1[l];
    const float* P0 = g_P + (size_t)(n * SEQ_LEN + t0) * NSTACK;
    const float* P1 = g_P + (size_t)(n * SEQ_LEN + t1) * NSTACK;

    float *ksd, *vsd;
    if (n < N_SUPPORT) {
        ksd = g_ks_s + (size_t)(n * L_TUP + l) * OUT_DIM;
        vsd = g_vs_s + (size_t)(n * L_TUP + l) * OUT_DIM;
    } else {
        int m = n - N_SUPPORT;
        ksd = g_ks_q + (size_t)(m * L_TUP + l) * OUT_DIM;
        vsd = g_vs_q + (size_t)(m * L_TUP + l) * OUT_DIM;
    }

    __shared__ float kbuf[OUT_DIM];
    float s = 0.f, s2 = 0.f;
    for (int o = threadIdx.x; o < OUT_DIM; o += blockDim.x) {
        float kv = P0[o] + P1[OUT_DIM + o] + k_b[o];
        kbuf[o] = kv; s += kv; s2 += kv * kv;
        vsd[o] = P0[2 * OUT_DIM + o] + P1[3 * OUT_DIM + o] + v_b[o];
    }
    int lane = threadIdx.x & 31, wid = threadIdx.x >> 5;
    #pragma unroll
    for (int off = 16; off; off >>= 1) {
        s  += __shfl_xor_sync(0xffffffffu, s,  off);
        s2 += __shfl_xor_sync(0xffffffffu, s2, off);
    }
    __shared__ float ws[8], ws2[8], sm_mean, sm_rstd;
    if (lane == 0) { ws[wid] = s; ws2[wid] = s2; }
    __syncthreads();
    if (threadIdx.x == 0) {
        float S = 0.f, S2 = 0.f;
        #pragma unroll
        for (int w = 0; w < 8; w++) { S += ws[w]; S2 += ws2[w]; }
        float mean = S / (float)OUT_DIM;
        float var  = S2 / (float)OUT_DIM - mean * mean;
        sm_mean = mean; sm_rstd = rsqrtf(var + 1e-5f);
    }
    __syncthreads();
    float mean = sm_mean, rstd = sm_rstd;
    for (int o = threadIdx.x; o < OUT_DIM; o += blockDim.x)
        ksd[o] = (kbuf[o] - mean) * rstd * ln_g[o] + ln_b[o];
}

// ---------------------------------------------------------------------------
// per-row blockwise softmax (5 warps, one class segment each)
// ---------------------------------------------------------------------------
__global__ __launch_bounds__(160)
void softmax_kernel()
{
    int row = blockIdx.x;
    int warp = threadIdx.x >> 5, lane = threadIdx.x & 31;
    float* p = g_S + (size_t)row * ROWS_S + warp * SEG;
    float v[5]; float mx = -INFINITY;
    #pragma unroll
    for (int i = 0; i < 5; i++) {
        int c = lane + 32 * i;
        v[i] = (c < SEG) ? p[c] : -INFINITY;
        mx = fmaxf(mx, v[i]);
    }
    #pragma unroll
    for (int off = 16; off; off >>= 1)
        mx = fmaxf(mx, __shfl_xor_sync(0xffffffffu, mx, off));
    float sm = 0.f;
    #pragma unroll
    for (int i = 0; i < 5; i++) {
        int c = lane + 32 * i;
        v[i] = (c < SEG) ? expf(v[i] - mx) : 0.f;
        sm += v[i];
    }
    #pragma unroll
    for (int off = 16; off; off >>= 1)
        sm += __shfl_xor_sync(0xffffffffu, sm, off);
    float inv = 1.f / sm;
    #pragma unroll
    for (int i = 0; i < 5; i++) {
        int c = lane + 32 * i;
        if (c < SEG) p[c] = v[i] * inv;
    }
}

// ---------------------------------------------------------------------------
// per-query Gram matrix + distances -> sim, ori
// ---------------------------------------------------------------------------
__global__ __launch_bounds__(256)
void finalize_kernel(float* __restrict__ out)
{
    int q = blockIdx.x;
    const float* v = g_vs_q + (size_t)q * PLANE;
    const float* pp[WAY];
    #pragma unroll
    for (int w = 0; w < WAY; w++)
        pp[w] = g_proto + (size_t)w * ROWS_Q * OUT_DIM + (size_t)q * PLANE;

    float acc[21];
    #pragma unroll
    for (int i = 0; i < 21; i++) acc[i] = 0.f;

    for (int i = threadIdx.x; i < PLANE; i += blockDim.x) {
        float vv = v[i];
        float a0 = pp[0][i], a1 = pp[1][i], a2 = pp[2][i], a3 = pp[3][i], a4 = pp[4][i];
        acc[0]  += a0 * a0;  acc[1]  += a0 * a1;  acc[2]  += a0 * a2;
        acc[3]  += a0 * a3;  acc[4]  += a0 * a4;
        acc[5]  += a1 * a1;  acc[6]  += a1 * a2;  acc[7]  += a1 * a3;  acc[8]  += a1 * a4;
        acc[9]  += a2 * a2;  acc[10] += a2 * a3;  acc[11] += a2 * a4;
        acc[12] += a3 * a3;  acc[13] += a3 * a4;
        acc[14] += a4 * a4;
        acc[15] += vv * a0;  acc[16] += vv * a1;  acc[17] += vv * a2;
        acc[18] += vv * a3;  acc[19] += vv * a4;
        acc[20] += vv * vv;
    }

    int lane = threadIdx.x & 31, wid = threadIdx.x >> 5;
    __shared__ float part[21][8];
    #pragma unroll
    for (int i = 0; i < 21; i++) {
        float a = acc[i];
        #pragma unroll
        for (int off = 16; off; off >>= 1)
            a += __shfl_xor_sync(0xffffffffu, a, off);
        if (lane == 0) part[i][wid] = a;
    }
    __syncthreads();
    __shared__ float tot[21];
    if (threadIdx.x < 21) {
        float sSum = 0.f;
        #pragma unroll
        for (int w = 0; w < 8; w++) sSum += part[threadIdx.x][w];
        tot[threadIdx.x] = sSum;
    }
    __syncthreads();
    if (threadIdx.x == 0) {
        float G[WAY][WAY];
        int t = 0;
        for (int a = 0; a < WAY; a++)
            for (int b = a; b < WAY; b++) { G[a][b] = tot[t]; G[b][a] = tot[t]; t++; }
        float D[WAY];
        for (int w = 0; w < WAY; w++) D[w] = tot[15 + w];
        float VV = tot[20];
        float nrm[WAY];
        for (int w = 0; w < WAY; w++) nrm[w] = sqrtf(G[w][w]);
        for (int a = 0; a < WAY; a++)
            for (int b = 0; b < WAY; b++)
                out[q * WAY * WAY + a * WAY + b] =
                    G[a][b] / fmaxf(nrm[a] * nrm[b], 1e-8f);
        for (int w = 0; w < WAY; w++)
            out[N_QUERIES * WAY * WAY + q * WAY + w] =
                -(VV - 2.f * D[w] + G[w][w]) / (float)L_TUP;
    }
}

// ---------------------------------------------------------------------------
// Launch
// ---------------------------------------------------------------------------
extern "C" void kernel_launch(void* const* d_in, const int* in_sizes, int n_in,
                              void* d_out, int out_size)
{
    const float* support = (const float*)d_in[0];
    const float* queries = (const float*)d_in[2];
    const float* k_w  = (const float*)d_in[3];
    const float* k_b  = (const float*)d_in[4];
    const float* v_w  = (const float*)d_in[5];
    const float* v_b  = (const float*)d_in[6];
    const float* ln_g = (const float*)d_in[7];
    const float* ln_b = (const float*)d_in[8];
    float* out = (float*)d_out;

    float *X, *P, *kss, *ksq, *vss, *S, *proto;
    __nv_bfloat16 *Xhl, *Whl, *KQhl, *KShl, *Ahl, *Vhl;
    cudaGetSymbolAddress((void**)&X,     g_X);
    cudaGetSymbolAddress((void**)&Xhl,   g_Xhl);
    cudaGetSymbolAddress((void**)&Whl,   g_Whl);
    cudaGetSymbolAddress((void**)&P,     g_P);
    cudaGetSymbolAddress((void**)&kss,   g_ks_s);
    cudaGetSymbolAddress((void**)&ksq,   g_ks_q);
    cudaGetSymbolAddress((void**)&vss,   g_vs_s);
    cudaGetSymbolAddress((void**)&KQhl,  g_KQhl);
    cudaGetSymbolAddress((void**)&KShl,  g_KShl);
    cudaGetSymbolAddress((void**)&S,     g_S);
    cudaGetSymbolAddress((void**)&Ahl,   g_Ahl);
    cudaGetSymbolAddress((void**)&Vhl,   g_Vhl);
    cudaGetSymbolAddress((void**)&proto, g_proto);

    // 1. X = inputs + PE
    add_pe_kernel<<<(ROWS_X * D_MODEL + 255) / 256, 256>>>(support, queries);
    // 2. hi/lo conversions for projection GEMM
    conv_hilo<0><<<(ROWS_X * D_MODEL + 255) / 256, 256>>>(X, Xhl, ROWS_X, D_MODEL);
    convW_kernel<<<(NSTACK * D_MODEL + 255) / 256, 256>>>(k_w, v_w);
    // 3. P = X @ Wt^T  [1800, 4608], K=6144
    {
        dim3 grid(NSTACK / 128, (ROWS_X + 127) / 128);
        gemm_mma<<<grid, 256>>>(Xhl, Whl, P, ROWS_X, NSTACK, KBIG, 1.0f);
    }
    // 4. assemble ks (LayerNorm) / vs
    assemble_kernel<<<N_TOTAL * L_TUP, 256>>>(k_b, v_b, ln_g, ln_b);
    // 5. hi/lo for scores GEMM
    conv_hilo<0><<<(ROWS_Q * OUT_DIM + 255) / 256, 256>>>(ksq, KQhl, ROWS_Q, OUT_DIM);
    conv_hilo<1><<<(ROWS_S * OUT_DIM + 255) / 256, 256>>>(kss, KShl, ROWS_S, OUT_DIM);
    // 6. scores = ks_q @ ks_s^T / sqrt(OUT_DIM)  [5600, 700], K=3456
    {
        dim3 grid((ROWS_S + 127) / 128, (ROWS_Q + 127) / 128);
        gemm_mma<<<grid, 256>>>(KQhl, KShl, S, ROWS_Q, ROWS_S, KSC,
                                1.0f / sqrtf((float)OUT_DIM));
    }
    // 7. softmax (in place)
    softmax_kernel<<<ROWS_Q, 160>>>();
    // 8. hi/lo for proto GEMMs
    conv_attn_kernel<<<(WAY * ROWS_Q * KPR + 255) / 256, 256>>>();
    conv_vsT_kernel<<<(WAY * OUT_DIM * KPR + 255) / 256, 256>>>();
    // 9. proto[w] = attn_w @ vs_w  [5600, 1152], K=448
    {
        dim3 grid(OUT_DIM / 128, (ROWS_Q + 127) / 128);
        for (int w = 0; w < WAY; w++) {
            gemm_mma<<<grid, 256>>>(
                Ahl + (size_t)w * ROWS_Q * KPR,
                Vhl + (size_t)w * OUT_DIM * KPR,
                proto + (size_t)w * ROWS_Q * OUT_DIM,
                ROWS_Q, OUT_DIM, KPR, 1.0f);
        }
    }
    // 10. finalize
    finalize_kernel<<<N_QUERIES, 256>>>(out);
}

// round 4
// speedup vs baseline: 5.4043x; 1.3345x over previous
#include <cuda_runtime.h>
#include <cuda_bf16.h>
#include <math.h>
#include <stdint.h>

// ---------------------------------------------------------------------------
// Problem constants
// ---------------------------------------------------------------------------
#define SEQ_LEN   8
#define D_MODEL   2048
#define OUT_DIM   1152
#define WAY       5
#define SHOT      5
#define N_SUPPORT 25
#define N_QUERIES 200
#define N_TOTAL   225
#define L_TUP     28
#define TWO_D     4096
#define NSTACK    4608          // 4 * OUT_DIM (k h0, k h1, v h0, v h1)
#define ROWS_X    1800          // N_TOTAL * SEQ_LEN
#define ROWS_Q    5600          // N_QUERIES * L_TUP
#define ROWS_S    700           // N_SUPPORT * L_TUP
#define SEG       140           // SHOT * L_TUP
#define PLANE     32256         // L_TUP * OUT_DIM

// hi/lo-split K sizes (3x, multiple of 32)
#define KBIG      6144          // 3 * 2048
#define KSC       3456          // 3 * 1152
#define KPR       448           // 3 * 140 = 420, padded to 448

__constant__ int c_t0[L_TUP] = {0,0,0,0,0,0,0,1,1,1,1,1,1,2,2,2,2,2,3,3,3,3,4,4,4,5,5,6};
__constant__ int c_t1[L_TUP] = {1,2,3,4,5,6,7,2,3,4,5,6,7,3,4,5,6,7,4,5,6,7,5,6,7,6,7,7};

// ---------------------------------------------------------------------------
// Scratch (device globals; no allocation allowed)
// ---------------------------------------------------------------------------
__device__ __nv_bfloat16  g_Xhl[(size_t)ROWS_X * KBIG];     // A-layout (hi,hi,lo)
__device__ __nv_bfloat16  g_Whl[(size_t)NSTACK * KBIG];     // B-layout (hi,lo,hi)
__device__ float          g_P[(size_t)ROWS_X * NSTACK];
__device__ float          g_ks_s[ROWS_S * OUT_DIM];
__device__ float          g_ks_q[ROWS_Q * OUT_DIM];
__device__ float          g_vs_s[ROWS_S * OUT_DIM];
__device__ float          g_vs_q[ROWS_Q * OUT_DIM];
__device__ __nv_bfloat16  g_KQhl[(size_t)ROWS_Q * KSC];     // A-layout
__device__ __nv_bfloat16  g_KShl[(size_t)ROWS_S * KSC];     // B-layout
__device__ float          g_S[(size_t)ROWS_Q * ROWS_S];     // scores -> attn in place
__device__ __nv_bfloat16  g_Ahl[(size_t)WAY * ROWS_Q * KPR];   // attn slices, A-layout
__device__ __nv_bfloat16  g_Vhl[(size_t)WAY * OUT_DIM * KPR];  // vs_s^T slices, B-layout
__device__ float          g_proto[(size_t)WAY * ROWS_Q * OUT_DIM];

// ---------------------------------------------------------------------------
// Helpers
// ---------------------------------------------------------------------------
__device__ __forceinline__ uint32_t smem_u32(const void* p) {
    uint32_t a;
    asm("{ .reg .u64 t; cvta.to.shared.u64 t, %1; cvt.u32.u64 %0, t; }"
        : "=r"(a) : "l"(p));
    return a;
}

#define CP16(dst, src) \
    asm volatile("cp.async.cg.shared.global [%0], [%1], 16;" :: "r"(dst), "l"(src))
#define CP_COMMIT() asm volatile("cp.async.commit_group;" ::: "memory")
#define CP_WAIT(n)  asm volatile("cp.async.wait_group %0;" :: "n"(n) : "memory")

// ---------------------------------------------------------------------------
// mma.sync bf16 GEMM: C[M,N] = alpha * A[M,K] * B[N,K]^T   (A,B K-major bf16)
// 128x128 CTA tile, BK=32, 3-stage cp.async pipeline, single barrier per
// chunk (wait -> barrier -> issue -> compute), 8 warps (2x4), warp tile
// 64x32 via m16n8k16. Batched over blockIdx.z via strides. 2 CTAs/SM.
// K must be a multiple of 32. OOB rows clamped (outputs never stored).
// ---------------------------------------------------------------------------
__global__ __launch_bounds__(256, 2)
void gemm_mma(const __nv_bfloat16* __restrict__ A, const __nv_bfloat16* __restrict__ B,
              float* __restrict__ C, int M, int N, int K, float alpha,
              size_t aStride, size_t bStride, size_t cStride)
{
    __shared__ uint4 sbuf[3][1024];    // per stage: [0..511]=A (8KB), [512..1023]=B

    A += (size_t)blockIdx.z * aStride;
    B += (size_t)blockIdx.z * bStride;
    C += (size_t)blockIdx.z * cStride;

    const int tid  = threadIdx.x;
    const int lane = tid & 31;
    const int wid  = tid >> 5;
    const int wm   = wid >> 2;         // 0..1  (warp row)
    const int wn   = wid & 3;          // 0..3  (warp col)
    const int row0 = blockIdx.y * 128;
    const int col0 = blockIdx.x * 128;

    // loader mapping: thread handles A chunks {tid, tid+256}, B chunks {tid, tid+256}
    // chunk ch (0..511): row = ch>>2, cq = ch&3 (16B column chunk)
    int l_sw[2];
    const __nv_bfloat16 *gA[2], *gB[2];
    #pragma unroll
    for (int i = 0; i < 2; i++) {
        int ch  = tid + i * 256;
        int row = ch >> 2, cq = ch & 3;
        l_sw[i] = row * 4 + ((cq ^ (row >> 1)) & 3);
        int ra = row0 + row; if (ra > M - 1) ra = M - 1;
        int rb = col0 + row; if (rb > N - 1) rb = N - 1;
        gA[i] = A + (size_t)ra * K + cq * 8;
        gB[i] = B + (size_t)rb * K + cq * 8;
    }

    const int NC = K >> 5;

    auto issue = [&](int stage, int c) {
        uint32_t base = smem_u32(&sbuf[stage][0]);
        #pragma unroll
        for (int i = 0; i < 2; i++) {
            CP16(base +        l_sw[i] * 16, gA[i] + c * 32);
            CP16(base + 8192 + l_sw[i] * 16, gB[i] + c * 32);
        }
        CP_COMMIT();
    };

    float acc[4][4][4];
    #pragma unroll
    for (int mi = 0; mi < 4; mi++)
        #pragma unroll
        for (int ni = 0; ni < 4; ni++)
            #pragma unroll
            for (int e = 0; e < 4; e++) acc[mi][ni][e] = 0.f;

    const int q = lane >> 3;           // 0..3 (ldmatrix quad)
    const int r = lane & 7;

    auto compute = [&](int stage) {
        uint32_t abase = smem_u32(&sbuf[stage][0]);
        uint32_t bbase = abase + 8192;
        #pragma unroll
        for (int ks = 0; ks < 2; ks++) {
            uint32_t af[4][4];
            #pragma unroll
            for (int mi = 0; mi < 4; mi++) {
                int row = wm * 64 + mi * 16 + r + (q & 1) * 8;
                int cq  = ks * 2 + (q >> 1);
                uint32_t ad = abase + (uint32_t)(row * 4 + ((cq ^ (row >> 1)) & 3)) * 16u;
                asm volatile("ldmatrix.sync.aligned.m8n8.x4.shared.b16 {%0,%1,%2,%3}, [%4];"
                    : "=r"(af[mi][0]), "=r"(af[mi][1]), "=r"(af[mi][2]), "=r"(af[mi][3])
                    : "r"(ad));
            }
            uint32_t bf[4][2];
            #pragma unroll
            for (int nh = 0; nh < 2; nh++) {
                int ni  = nh * 2 + (q >> 1);
                int row = wn * 32 + ni * 8 + r;
                int cq  = ks * 2 + (q & 1);
                uint32_t bd = bbase + (uint32_t)(row * 4 + ((cq ^ (row >> 1)) & 3)) * 16u;
                asm volatile("ldmatrix.sync.aligned.m8n8.x4.shared.b16 {%0,%1,%2,%3}, [%4];"
                    : "=r"(bf[nh*2][0]), "=r"(bf[nh*2][1]),
                      "=r"(bf[nh*2+1][0]), "=r"(bf[nh*2+1][1])
                    : "r"(bd));
            }
            #pragma unroll
            for (int mi = 0; mi < 4; mi++)
                #pragma unroll
                for (int ni = 0; ni < 4; ni++) {
                    asm volatile(
                        "mma.sync.aligned.m16n8k16.row.col.f32.bf16.bf16.f32 "
                        "{%0,%1,%2,%3}, {%4,%5,%6,%7}, {%8,%9}, {%0,%1,%2,%3};"
                        : "+f"(acc[mi][ni][0]), "+f"(acc[mi][ni][1]),
                          "+f"(acc[mi][ni][2]), "+f"(acc[mi][ni][3])
                        : "r"(af[mi][0]), "r"(af[mi][1]), "r"(af[mi][2]), "r"(af[mi][3]),
                          "r"(bf[ni][0]), "r"(bf[ni][1]));
                }
        }
    };

    // 3-stage pipeline: wait -> barrier -> issue(c+2) -> compute(c)
    issue(0, 0);
    if (NC > 1) issue(1, 1);
    for (int c = 0; c < NC; c++) {
        if (c + 1 < NC) CP_WAIT(1);
        else            CP_WAIT(0);
        __syncthreads();
        if (c + 2 < NC) issue((c + 2) % 3, c + 2);
        compute(c % 3);
    }

    // epilogue: float2 stores
    const int g  = lane >> 2;
    const int tg = lane & 3;
    #pragma unroll
    for (int mi = 0; mi < 4; mi++) {
        int rr0 = row0 + wm * 64 + mi * 16 + g;
        int rr1 = rr0 + 8;
        #pragma unroll
        for (int ni = 0; ni < 4; ni++) {
            int cc = col0 + wn * 32 + ni * 8 + tg * 2;
            if (cc < N) {
                if (rr0 < M) {
                    float2 v = make_float2(alpha * acc[mi][ni][0], alpha * acc[mi][ni][1]);
                    *(float2*)(C + (size_t)rr0 * N + cc) = v;
                }
                if (rr1 < M) {
                    float2 v = make_float2(alpha * acc[mi][ni][2], alpha * acc[mi][ni][3]);
                    *(float2*)(C + (size_t)rr1 * N + cc) = v;
                }
            }
        }
    }
}

// ---------------------------------------------------------------------------
// hi/lo split helpers
// ---------------------------------------------------------------------------
__device__ __forceinline__ void split2(float x, __nv_bfloat16& hi, __nv_bfloat16& lo) {
    hi = __float2bfloat16(x);
    lo = __float2bfloat16(x - __bfloat162float(hi));
}

// Fused: X = [support; queries] + PE, then hi/lo split -> A-layout (hi,hi,lo)
__global__ void conv_pe_hilo(const float* __restrict__ support,
                             const float* __restrict__ queries)
{
    int e = blockIdx.x * blockDim.x + threadIdx.x;
    if (e >= ROWS_X * D_MODEL) return;
    int n = e / (SEQ_LEN * D_MODEL);
    int rem = e % (SEQ_LEN * D_MODEL);
    int s = rem / D_MODEL, d = rem % D_MODEL;
    const float c = -9.210340371976184f / (float)D_MODEL;
    float div = expf((float)(2 * (d >> 1)) * c);
    float arg = (float)s * div;
    float pe = ((d & 1) ? cosf(arg) : sinf(arg)) * 0.1f;
    float x = ((n < N_SUPPORT) ? support[e]
                               : queries[e - N_SUPPORT * SEQ_LEN * D_MODEL]) + pe;
    __nv_bfloat16 hi, lo; split2(x, hi, lo);
    int row = e / D_MODEL;
    __nv_bfloat16* o = g_Xhl + (size_t)row * KBIG;
    o[d] = hi; o[D_MODEL + d] = hi; o[2 * D_MODEL + d] = lo;
}

// ORDER 0: A-layout (hi, hi, lo);  ORDER 1: B-layout (hi, lo, hi)
template<int ORDER>
__global__ void conv_hilo(const float* __restrict__ in, __nv_bfloat16* __restrict__ out,
                          int R, int Kin)
{
    int e = blockIdx.x * blockDim.x + threadIdx.x;
    if (e >= R * Kin) return;
    int r = e / Kin, k = e % Kin;
    __nv_bfloat16 hi, lo; split2(in[e], hi, lo);
    __nv_bfloat16* o = out + (size_t)r * (3 * Kin);
    o[k] = hi;
    o[Kin + k]     = (ORDER == 0) ? hi : lo;
    o[2 * Kin + k] = (ORDER == 0) ? lo : hi;
}

// stacked weights -> B-layout hi/lo
__global__ void convW_kernel(const float* __restrict__ k_w, const float* __restrict__ v_w)
{
    int e = blockIdx.x * blockDim.x + threadIdx.x;
    if (e >= NSTACK * D_MODEL) return;
    int j = e / D_MODEL, k = e % D_MODEL;
    int part = j / OUT_DIM, o = j % OUT_DIM;
    const float* w = (part < 2) ? k_w : v_w;
    float x = w[(size_t)o * TWO_D + (part & 1) * D_MODEL + k];
    __nv_bfloat16 hi, lo; split2(x, hi, lo);
    __nv_bfloat16* dst = g_Whl + (size_t)j * KBIG;
    dst[k] = hi; dst[D_MODEL + k] = lo; dst[2 * D_MODEL + k] = hi;
}

// attn slices -> A-layout [WAY][ROWS_Q][KPR] (hi, hi, lo), pad to 448 with 0
__global__ void conv_attn_kernel()
{
    int e = blockIdx.x * blockDim.x + threadIdx.x;
    const int total = WAY * ROWS_Q * KPR;
    if (e >= total) return;
    int w = e / (ROWS_Q * KPR);
    int rem = e % (ROWS_Q * KPR);
    int r = rem / KPR, j = rem % KPR;
    __nv_bfloat16 v = __float2bfloat16(0.f);
    if (j < 420) {
        int seg = j / SEG, jj = j - seg * SEG;
        float x = g_S[(size_t)r * ROWS_S + w * SEG + jj];
        __nv_bfloat16 hi, lo; split2(x, hi, lo);
        v = (seg == 2) ? lo : hi;
    }
    g_Ahl[e] = v;
}

// vs_s^T slices -> B-layout [WAY][OUT_DIM][KPR] (hi, lo, hi)
__global__ void conv_vsT_kernel()
{
    int e = blockIdx.x * blockDim.x + threadIdx.x;
    const int total = WAY * OUT_DIM * KPR;
    if (e >= total) return;
    int w = e / (OUT_DIM * KPR);
    int rem = e % (OUT_DIM * KPR);
    int d = rem / KPR, j = rem % KPR;
    __nv_bfloat16 v = __float2bfloat16(0.f);
    if (j < 420) {
        int seg = j / SEG, jj = j - seg * SEG;
        float x = g_vs_s[(size_t)(w * SEG + jj) * OUT_DIM + d];
        __nv_bfloat16 hi, lo; split2(x, hi, lo);
        v = (seg == 1) ? lo : hi;
    }
    g_Vhl[e] = v;
}

// ---------------------------------------------------------------------------
// assemble tuple features + LayerNorm(k), plain v
// ---------------------------------------------------------------------------
__global__ __launch_bounds__(256)
void assemble_kernel(const float* __restrict__ k_b, const float* __restrict__ v_b,
                     const float* __restrict__ ln_g, const float* __restrict__ ln_b)
{
    int rl = blockIdx.x;
    int n = rl / L_TUP, l = rl % L_TUP;
    int t0 = c_t0[l], t1 = c_t1[l];
    const float* P0 = g_P + (size_t)(n * SEQ_LEN + t0) * NSTACK;
    const float* P1 = g_P + (size_t)(n * SEQ_LEN + t1) * NSTACK;

    float *ksd, *vsd;
    if (n < N_SUPPORT) {
        ksd = g_ks_s + (size_t)(n * L_TUP + l) * OUT_DIM;
        vsd = g_vs_s + (size_t)(n * L_TUP + l) * OUT_DIM;
    } else {
        int m = n - N_SUPPORT;
        ksd = g_ks_q + (size_t)(m * L_TUP + l) * OUT_DIM;
        vsd = g_vs_q + (size_t)(m * L_TUP + l) * OUT_DIM;
    }

    __shared__ float kbuf[OUT_DIM];
    float s = 0.f, s2 = 0.f;
    for (int o = threadIdx.x; o < OUT_DIM; o += blockDim.x) {
        float kv = P0[o] + P1[OUT_DIM + o] + k_b[o];
        kbuf[o] = kv; s += kv; s2 += kv * kv;
        vsd[o] = P0[2 * OUT_DIM + o] + P1[3 * OUT_DIM + o] + v_b[o];
    }
    int lane = threadIdx.x & 31, wid = threadIdx.x >> 5;
    #pragma unroll
    for (int off = 16; off; off >>= 1) {
        s  += __shfl_xor_sync(0xffffffffu, s,  off);
        s2 += __shfl_xor_sync(0xffffffffu, s2, off);
    }
    __shared__ float ws[8], ws2[8], sm_mean, sm_rstd;
    if (lane == 0) { ws[wid] = s; ws2[wid] = s2; }
    __syncthreads();
    if (threadIdx.x == 0) {
        float S = 0.f, S2 = 0.f;
        #pragma unroll
        for (int w = 0; w < 8; w++) { S += ws[w]; S2 += ws2[w]; }
        float mean = S / (float)OUT_DIM;
        float var  = S2 / (float)OUT_DIM - mean * mean;
        sm_mean = mean; sm_rstd = rsqrtf(var + 1e-5f);
    }
    __syncthreads();
    float mean = sm_mean, rstd = sm_rstd;
    for (int o = threadIdx.x; o < OUT_DIM; o += blockDim.x)
        ksd[o] = (kbuf[o] - mean) * rstd * ln_g[o] + ln_b[o];
}

// ---------------------------------------------------------------------------
// per-row blockwise softmax (5 warps, one class segment each)
// ---------------------------------------------------------------------------
__global__ __launch_bounds__(160)
void softmax_kernel()
{
    int row = blockIdx.x;
    int warp = threadIdx.x >> 5, lane = threadIdx.x & 31;
    float* p = g_S + (size_t)row * ROWS_S + warp * SEG;
    float v[5]; float mx = -INFINITY;
    #pragma unroll
    for (int i = 0; i < 5; i++) {
        int c = lane + 32 * i;
        v[i] = (c < SEG) ? p[c] : -INFINITY;
        mx = fmaxf(mx, v[i]);
    }
    #pragma unroll
    for (int off = 16; off; off >>= 1)
        mx = fmaxf(mx, __shfl_xor_sync(0xffffffffu, mx, off));
    float sm = 0.f;
    #pragma unroll
    for (int i = 0; i < 5; i++) {
        int c = lane + 32 * i;
        v[i] = (c < SEG) ? expf(v[i] - mx) : 0.f;
        sm += v[i];
    }
    #pragma unroll
    for (int off = 16; off; off >>= 1)
        sm += __shfl_xor_sync(0xffffffffu, sm, off);
    float inv = 1.f / sm;
    #pragma unroll
    for (int i = 0; i < 5; i++) {
        int c = lane + 32 * i;
        if (c < SEG) p[c] = v[i] * inv;
    }
}

// ---------------------------------------------------------------------------
// per-query Gram matrix + distances -> sim, ori
// ---------------------------------------------------------------------------
__global__ __launch_bounds__(256)
void finalize_kernel(float* __restrict__ out)
{
    int q = blockIdx.x;
    const float* v = g_vs_q + (size_t)q * PLANE;
    const float* pp[WAY];
    #pragma unroll
    for (int w = 0; w < WAY; w++)
        pp[w] = g_proto + (size_t)w * ROWS_Q * OUT_DIM + (size_t)q * PLANE;

    float acc[21];
    #pragma unroll
    for (int i = 0; i < 21; i++) acc[i] = 0.f;

    for (int i = threadIdx.x; i < PLANE; i += blockDim.x) {
        float vv = v[i];
        float a0 = pp[0][i], a1 = pp[1][i], a2 = pp[2][i], a3 = pp[3][i], a4 = pp[4][i];
        acc[0]  += a0 * a0;  acc[1]  += a0 * a1;  acc[2]  += a0 * a2;
        acc[3]  += a0 * a3;  acc[4]  += a0 * a4;
        acc[5]  += a1 * a1;  acc[6]  += a1 * a2;  acc[7]  += a1 * a3;  acc[8]  += a1 * a4;
        acc[9]  += a2 * a2;  acc[10] += a2 * a3;  acc[11] += a2 * a4;
        acc[12] += a3 * a3;  acc[13] += a3 * a4;
        acc[14] += a4 * a4;
        acc[15] += vv * a0;  acc[16] += vv * a1;  acc[17] += vv * a2;
        acc[18] += vv * a3;  acc[19] += vv * a4;
        acc[20] += vv * vv;
    }

    int lane = threadIdx.x & 31, wid = threadIdx.x >> 5;
    __shared__ float part[21][8];
    #pragma unroll
    for (int i = 0; i < 21; i++) {
        float a = acc[i];
        #pragma unroll
        for (int off = 16; off; off >>= 1)
            a += __shfl_xor_sync(0xffffffffu, a, off);
        if (lane == 0) part[i][wid] = a;
    }
    __syncthreads();
    __shared__ float tot[21];
    if (threadIdx.x < 21) {
        float sSum = 0.f;
        #pragma unroll
        for (int w = 0; w < 8; w++) sSum += part[threadIdx.x][w];
        tot[threadIdx.x] = sSum;
    }
    __syncthreads();
    if (threadIdx.x == 0) {
        float G[WAY][WAY];
        int t = 0;
        for (int a = 0; a < WAY; a++)
            for (int b = a; b < WAY; b++) { G[a][b] = tot[t]; G[b][a] = tot[t]; t++; }
        float D[WAY];
        for (int w = 0; w < WAY; w++) D[w] = tot[15 + w];
        float VV = tot[20];
        float nrm[WAY];
        for (int w = 0; w < WAY; w++) nrm[w] = sqrtf(G[w][w]);
        for (int a = 0; a < WAY; a++)
            for (int b = 0; b < WAY; b++)
                out[q * WAY * WAY + a * WAY + b] =
                    G[a][b] / fmaxf(nrm[a] * nrm[b], 1e-8f);
        for (int w = 0; w < WAY; w++)
            out[N_QUERIES * WAY * WAY + q * WAY + w] =
                -(VV - 2.f * D[w] + G[w][w]) / (float)L_TUP;
    }
}

// ---------------------------------------------------------------------------
// Launch
// ---------------------------------------------------------------------------
extern "C" void kernel_launch(void* const* d_in, const int* in_sizes, int n_in,
                              void* d_out, int out_size)
{
    const float* support = (const float*)d_in[0];
    const float* queries = (const float*)d_in[2];
    const float* k_w  = (const float*)d_in[3];
    const float* k_b  = (const float*)d_in[4];
    const float* v_w  = (const float*)d_in[5];
    const float* v_b  = (const float*)d_in[6];
    const float* ln_g = (const float*)d_in[7];
    const float* ln_b = (const float*)d_in[8];
    float* out = (float*)d_out;

    float *P, *kss, *ksq, *vss, *S, *proto;
    __nv_bfloat16 *Xhl, *Whl, *KQhl, *KShl, *Ahl, *Vhl;
    cudaGetSymbolAddress((void**)&Xhl,   g_Xhl);
    cudaGetSymbolAddress((void**)&Whl,   g_Whl);
    cudaGetSymbolAddress((void**)&P,     g_P);
    cudaGetSymbolAddress((void**)&kss,   g_ks_s);
    cudaGetSymbolAddress((void**)&ksq,   g_ks_q);
    cudaGetSymbolAddress((void**)&vss,   g_vs_s);
    cudaGetSymbolAddress((void**)&KQhl,  g_KQhl);
    cudaGetSymbolAddress((void**)&KShl,  g_KShl);
    cudaGetSymbolAddress((void**)&S,     g_S);
    cudaGetSymbolAddress((void**)&Ahl,   g_Ahl);
    cudaGetSymbolAddress((void**)&Vhl,   g_Vhl);
    cudaGetSymbolAddress((void**)&proto, g_proto);

    // 1. fused PE + hi/lo conversion; weight conversion
    conv_pe_hilo<<<(ROWS_X * D_MODEL + 255) / 256, 256>>>(support, queries);
    convW_kernel<<<(NSTACK * D_MODEL + 255) / 256, 256>>>(k_w, v_w);
    // 2. P = X @ Wt^T  [1800, 4608], K=6144
    {
        dim3 grid(NSTACK / 128, (ROWS_X + 127) / 128, 1);
        gemm_mma<<<grid, 256>>>(Xhl, Whl, P, ROWS_X, NSTACK, KBIG, 1.0f, 0, 0, 0);
    }
    // 3. assemble ks (LayerNorm) / vs
    assemble_kernel<<<N_TOTAL * L_TUP, 256>>>(k_b, v_b, ln_g, ln_b);
    // 4. hi/lo for scores GEMM
    conv_hilo<0><<<(ROWS_Q * OUT_DIM + 255) / 256, 256>>>(ksq, KQhl, ROWS_Q, OUT_DIM);
    conv_hilo<1><<<(ROWS_S * OUT_DIM + 255) / 256, 256>>>(kss, KShl, ROWS_S, OUT_DIM);
    // 5. scores = ks_q @ ks_s^T / sqrt(OUT_DIM)  [5600, 700], K=3456
    {
        dim3 grid((ROWS_S + 127) / 128, (ROWS_Q + 127) / 128, 1);
        gemm_mma<<<grid, 256>>>(KQhl, KShl, S, ROWS_Q, ROWS_S, KSC,
                                1.0f / sqrtf((float)OUT_DIM), 0, 0, 0);
    }
    // 6. softmax (in place)
    softmax_kernel<<<ROWS_Q, 160>>>();
    // 7. hi/lo for proto GEMMs
    conv_attn_kernel<<<(WAY * ROWS_Q * KPR + 255) / 256, 256>>>();
    conv_vsT_kernel<<<(WAY * OUT_DIM * KPR + 255) / 256, 256>>>();
    // 8. proto[w] = attn_w @ vs_w  [5600, 1152], K=448 — batched over z
    {
        dim3 grid(OUT_DIM / 128, (ROWS_Q + 127) / 128, WAY);
        gemm_mma<<<grid, 256>>>(Ahl, Vhl, proto, ROWS_Q, OUT_DIM, KPR, 1.0f,
                                (size_t)ROWS_Q * KPR,
                                (size_t)OUT_DIM * KPR,
                                (size_t)ROWS_Q * OUT_DIM);
    }
    // 9. finalize
    finalize_kernel<<<N_QUERIES, 256>>>(out);
}

// round 5
// speedup vs baseline: 5.8395x; 1.0805x over previous
#include <cuda_runtime.h>
#include <cuda_bf16.h>
#include <math.h>
#include <stdint.h>

// ---------------------------------------------------------------------------
// Problem constants
// ---------------------------------------------------------------------------
#define SEQ_LEN   8
#define D_MODEL   2048
#define OUT_DIM   1152
#define WAY       5
#define SHOT      5
#define N_SUPPORT 25
#define N_QUERIES 200
#define N_TOTAL   225
#define L_TUP     28
#define TWO_D     4096
#define NSTACK    4608          // 4 * OUT_DIM (k h0, k h1, v h0, v h1)
#define ROWS_X    1800          // N_TOTAL * SEQ_LEN
#define ROWS_Q    5600          // N_QUERIES * L_TUP
#define ROWS_S    700           // N_SUPPORT * L_TUP
#define SEG       140           // SHOT * L_TUP
#define PLANE     32256         // L_TUP * OUT_DIM

// hi/lo-split K sizes (3x, multiple of 32)
#define KBIG      6144          // 3 * 2048
#define KSC       3456          // 3 * 1152
#define KPR       448           // 3 * 140 = 420, padded to 448

__constant__ int c_t0[L_TUP] = {0,0,0,0,0,0,0,1,1,1,1,1,1,2,2,2,2,2,3,3,3,3,4,4,4,5,5,6};
__constant__ int c_t1[L_TUP] = {1,2,3,4,5,6,7,2,3,4,5,6,7,3,4,5,6,7,4,5,6,7,5,6,7,6,7,7};

// ---------------------------------------------------------------------------
// Scratch (device globals; no allocation allowed)
// ---------------------------------------------------------------------------
__device__ __nv_bfloat16  g_Xhl[(size_t)ROWS_X * KBIG];     // A-layout (hi,hi,lo)
__device__ __nv_bfloat16  g_Whl[(size_t)NSTACK * KBIG];     // B-layout (hi,lo,hi)
__device__ float          g_P[(size_t)ROWS_X * NSTACK];
__device__ float          g_vs_s[ROWS_S * OUT_DIM];
__device__ float          g_vs_q[ROWS_Q * OUT_DIM];
__device__ __nv_bfloat16  g_KQhl[(size_t)ROWS_Q * KSC];     // A-layout (from assemble)
__device__ __nv_bfloat16  g_KShl[(size_t)ROWS_S * KSC];     // B-layout (from assemble)
__device__ float          g_S[(size_t)ROWS_Q * ROWS_S];     // scores (read-only after gemm)
__device__ __nv_bfloat16  g_Ahl[(size_t)WAY * ROWS_Q * KPR];   // attn slices (from softmax)
__device__ __nv_bfloat16  g_Vhl[(size_t)WAY * OUT_DIM * KPR];  // vs_s^T slices, B-layout
__device__ float          g_proto[(size_t)WAY * ROWS_Q * OUT_DIM];

// ---------------------------------------------------------------------------
// Helpers
// ---------------------------------------------------------------------------
__device__ __forceinline__ uint32_t smem_u32(const void* p) {
    uint32_t a;
    asm("{ .reg .u64 t; cvta.to.shared.u64 t, %1; cvt.u32.u64 %0, t; }"
        : "=r"(a) : "l"(p));
    return a;
}

#define CP16(dst, src) \
    asm volatile("cp.async.cg.shared.global [%0], [%1], 16;" :: "r"(dst), "l"(src))
#define CP_COMMIT() asm volatile("cp.async.commit_group;" ::: "memory")
#define CP_WAIT(n)  asm volatile("cp.async.wait_group %0;" :: "n"(n) : "memory")

__device__ __forceinline__ void split2(float x, __nv_bfloat16& hi, __nv_bfloat16& lo) {
    hi = __float2bfloat16(x);
    lo = __float2bfloat16(x - __bfloat162float(hi));
}

// ---------------------------------------------------------------------------
// mma.sync bf16 GEMM: C[M,N] = alpha * A[M,K] * B[N,K]^T   (A,B K-major bf16)
// 128x128 CTA tile, BK=32, 4-stage cp.async pipeline, single barrier per
// chunk, 8 warps (2x4), warp tile 64x32 via m16n8k16. Batched over
// blockIdx.z via strides. 2 CTAs/SM. K multiple of 32. OOB rows clamped.
// ---------------------------------------------------------------------------
__global__ __launch_bounds__(256, 2)
void gemm_mma(const __nv_bfloat16* __restrict__ A, const __nv_bfloat16* __restrict__ B,
              float* __restrict__ C, int M, int N, int K, float alpha,
              size_t aStride, size_t bStride, size_t cStride)
{
    __shared__ uint4 sbuf[4][1024];    // per stage: [0..511]=A (8KB), [512..1023]=B

    A += (size_t)blockIdx.z * aStride;
    B += (size_t)blockIdx.z * bStride;
    C += (size_t)blockIdx.z * cStride;

    const int tid  = threadIdx.x;
    const int lane = tid & 31;
    const int wid  = tid >> 5;
    const int wm   = wid >> 2;         // 0..1  (warp row)
    const int wn   = wid & 3;          // 0..3  (warp col)
    const int row0 = blockIdx.y * 128;
    const int col0 = blockIdx.x * 128;

    // loader mapping: thread handles A chunks {tid, tid+256}, B chunks {tid, tid+256}
    int l_sw[2];
    const __nv_bfloat16 *gA[2], *gB[2];
    #pragma unroll
    for (int i = 0; i < 2; i++) {
        int ch  = tid + i * 256;
        int row = ch >> 2, cq = ch & 3;
        l_sw[i] = row * 4 + ((cq ^ (row >> 1)) & 3);
        int ra = row0 + row; if (ra > M - 1) ra = M - 1;
        int rb = col0 + row; if (rb > N - 1) rb = N - 1;
        gA[i] = A + (size_t)ra * K + cq * 8;
        gB[i] = B + (size_t)rb * K + cq * 8;
    }

    const int NC = K >> 5;

    auto issue = [&](int stage, int c) {
        uint32_t base = smem_u32(&sbuf[stage][0]);
        #pragma unroll
        for (int i = 0; i < 2; i++) {
            CP16(base +        l_sw[i] * 16, gA[i] + c * 32);
            CP16(base + 8192 + l_sw[i] * 16, gB[i] + c * 32);
        }
        CP_COMMIT();
    };

    float acc[4][4][4];
    #pragma unroll
    for (int mi = 0; mi < 4; mi++)
        #pragma unroll
        for (int ni = 0; ni < 4; ni++)
            #pragma unroll
            for (int e = 0; e < 4; e++) acc[mi][ni][e] = 0.f;

    const int q = lane >> 3;           // 0..3 (ldmatrix quad)
    const int r = lane & 7;

    auto compute = [&](int stage) {
        uint32_t abase = smem_u32(&sbuf[stage][0]);
        uint32_t bbase = abase + 8192;
        #pragma unroll
        for (int ks = 0; ks < 2; ks++) {
            uint32_t af[4][4];
            #pragma unroll
            for (int mi = 0; mi < 4; mi++) {
                int row = wm * 64 + mi * 16 + r + (q & 1) * 8;
                int cq  = ks * 2 + (q >> 1);
                uint32_t ad = abase + (uint32_t)(row * 4 + ((cq ^ (row >> 1)) & 3)) * 16u;
                asm volatile("ldmatrix.sync.aligned.m8n8.x4.shared.b16 {%0,%1,%2,%3}, [%4];"
                    : "=r"(af[mi][0]), "=r"(af[mi][1]), "=r"(af[mi][2]), "=r"(af[mi][3])
                    : "r"(ad));
            }
            uint32_t bf[4][2];
            #pragma unroll
            for (int nh = 0; nh < 2; nh++) {
                int ni  = nh * 2 + (q >> 1);
                int row = wn * 32 + ni * 8 + r;
                int cq  = ks * 2 + (q & 1);
                uint32_t bd = bbase + (uint32_t)(row * 4 + ((cq ^ (row >> 1)) & 3)) * 16u;
                asm volatile("ldmatrix.sync.aligned.m8n8.x4.shared.b16 {%0,%1,%2,%3}, [%4];"
                    : "=r"(bf[nh*2][0]), "=r"(bf[nh*2][1]),
                      "=r"(bf[nh*2+1][0]), "=r"(bf[nh*2+1][1])
                    : "r"(bd));
            }
            #pragma unroll
            for (int mi = 0; mi < 4; mi++)
                #pragma unroll
                for (int ni = 0; ni < 4; ni++) {
                    asm volatile(
                        "mma.sync.aligned.m16n8k16.row.col.f32.bf16.bf16.f32 "
                        "{%0,%1,%2,%3}, {%4,%5,%6,%7}, {%8,%9}, {%0,%1,%2,%3};"
                        : "+f"(acc[mi][ni][0]), "+f"(acc[mi][ni][1]),
                          "+f"(acc[mi][ni][2]), "+f"(acc[mi][ni][3])
                        : "r"(af[mi][0]), "r"(af[mi][1]), "r"(af[mi][2]), "r"(af[mi][3]),
                          "r"(bf[ni][0]), "r"(bf[ni][1]));
                }
        }
    };

    // 4-stage pipeline: wait -> barrier -> issue(c+3) -> compute(c)
    issue(0, 0);
    if (NC > 1) issue(1, 1);
    if (NC > 2) issue(2, 2);
    for (int c = 0; c < NC; c++) {
        if (c + 2 < NC)      CP_WAIT(2);
        else if (c + 1 < NC) CP_WAIT(1);
        else                 CP_WAIT(0);
        __syncthreads();
        if (c + 3 < NC) issue((c + 3) & 3, c + 3);
        compute(c & 3);
    }

    // epilogue: float2 stores
    const int g  = lane >> 2;
    const int tg = lane & 3;
    #pragma unroll
    for (int mi = 0; mi < 4; mi++) {
        int rr0 = row0 + wm * 64 + mi * 16 + g;
        int rr1 = rr0 + 8;
        #pragma unroll
        for (int ni = 0; ni < 4; ni++) {
            int cc = col0 + wn * 32 + ni * 8 + tg * 2;
            if (cc < N) {
                if (rr0 < M) {
                    float2 v = make_float2(alpha * acc[mi][ni][0], alpha * acc[mi][ni][1]);
                    *(float2*)(C + (size_t)rr0 * N + cc) = v;
                }
                if (rr1 < M) {
                    float2 v = make_float2(alpha * acc[mi][ni][2], alpha * acc[mi][ni][3]);
                    *(float2*)(C + (size_t)rr1 * N + cc) = v;
                }
            }
        }
    }
}

// ---------------------------------------------------------------------------
// Fused: X = [support; queries] + PE, then hi/lo split -> A-layout (hi,hi,lo)
// ---------------------------------------------------------------------------
__global__ void conv_pe_hilo(const float* __restrict__ support,
                             const float* __restrict__ queries)
{
    int e = blockIdx.x * blockDim.x + threadIdx.x;
    if (e >= ROWS_X * D_MODEL) return;
    int n = e / (SEQ_LEN * D_MODEL);
    int rem = e % (SEQ_LEN * D_MODEL);
    int s = rem / D_MODEL, d = rem % D_MODEL;
    const float c = -9.210340371976184f / (float)D_MODEL;
    float div = expf((float)(2 * (d >> 1)) * c);
    float arg = (float)s * div;
    float pe = ((d & 1) ? cosf(arg) : sinf(arg)) * 0.1f;
    float x = ((n < N_SUPPORT) ? support[e]
                               : queries[e - N_SUPPORT * SEQ_LEN * D_MODEL]) + pe;
    __nv_bfloat16 hi, lo; split2(x, hi, lo);
    int row = e / D_MODEL;
    __nv_bfloat16* o = g_Xhl + (size_t)row * KBIG;
    o[d] = hi; o[D_MODEL + d] = hi; o[2 * D_MODEL + d] = lo;
}

// stacked weights -> B-layout hi/lo (hi, lo, hi)
__global__ void convW_kernel(const float* __restrict__ k_w, const float* __restrict__ v_w)
{
    int e = blockIdx.x * blockDim.x + threadIdx.x;
    if (e >= NSTACK * D_MODEL) return;
    int j = e / D_MODEL, k = e % D_MODEL;
    int part = j / OUT_DIM, o = j % OUT_DIM;
    const float* w = (part < 2) ? k_w : v_w;
    float x = w[(size_t)o * TWO_D + (part & 1) * D_MODEL + k];
    __nv_bfloat16 hi, lo; split2(x, hi, lo);
    __nv_bfloat16* dst = g_Whl + (size_t)j * KBIG;
    dst[k] = hi; dst[D_MODEL + k] = lo; dst[2 * D_MODEL + k] = hi;
}

// vs_s^T slices -> B-layout [WAY][OUT_DIM][KPR] (hi, lo, hi)
__global__ void conv_vsT_kernel()
{
    int e = blockIdx.x * blockDim.x + threadIdx.x;
    const int total = WAY * OUT_DIM * KPR;
    if (e >= total) return;
    int w = e / (OUT_DIM * KPR);
    int rem = e % (OUT_DIM * KPR);
    int d = rem / KPR, j = rem % KPR;
    __nv_bfloat16 v = __float2bfloat16(0.f);
    if (j < 420) {
        int seg = j / SEG, jj = j - seg * SEG;
        float x = g_vs_s[(size_t)(w * SEG + jj) * OUT_DIM + d];
        __nv_bfloat16 hi, lo; split2(x, hi, lo);
        v = (seg == 1) ? lo : hi;
    }
    g_Vhl[e] = v;
}

// ---------------------------------------------------------------------------
// assemble tuple features + LayerNorm(k) -> split bf16 layouts, plain v.
// support rows -> KShl (B-layout hi,lo,hi); query rows -> KQhl (A-layout hi,hi,lo)
// ---------------------------------------------------------------------------
__global__ __launch_bounds__(256)
void assemble_kernel(const float* __restrict__ k_b, const float* __restrict__ v_b,
                     const float* __restrict__ ln_g, const float* __restrict__ ln_b)
{
    int rl = blockIdx.x;
    int n = rl / L_TUP, l = rl % L_TUP;
    int t0 = c_t0[l], t1 = c_t1[l];
    const float* P0 = g_P + (size_t)(n * SEQ_LEN + t0) * NSTACK;
    const float* P1 = g_P + (size_t)(n * SEQ_LEN + t1) * NSTACK;

    const bool isSup = (n < N_SUPPORT);
    __nv_bfloat16* kd;
    float* vsd;
    if (isSup) {
        kd  = g_KShl + (size_t)(n * L_TUP + l) * KSC;
        vsd = g_vs_s + (size_t)(n * L_TUP + l) * OUT_DIM;
    } else {
        int m = n - N_SUPPORT;
        kd  = g_KQhl + (size_t)(m * L_TUP + l) * KSC;
        vsd = g_vs_q + (size_t)(m * L_TUP + l) * OUT_DIM;
    }

    __shared__ float kbuf[OUT_DIM];
    float s = 0.f, s2 = 0.f;
    for (int o = threadIdx.x; o < OUT_DIM; o += blockDim.x) {
        float kv = P0[o] + P1[OUT_DIM + o] + k_b[o];
        kbuf[o] = kv; s += kv; s2 += kv * kv;
        vsd[o] = P0[2 * OUT_DIM + o] + P1[3 * OUT_DIM + o] + v_b[o];
    }
    int lane = threadIdx.x & 31, wid = threadIdx.x >> 5;
    #pragma unroll
    for (int off = 16; off; off >>= 1) {
        s  += __shfl_xor_sync(0xffffffffu, s,  off);
        s2 += __shfl_xor_sync(0xffffffffu, s2, off);
    }
    __shared__ float ws[8], ws2[8], sm_mean, sm_rstd;
    if (lane == 0) { ws[wid] = s; ws2[wid] = s2; }
    __syncthreads();
    if (threadIdx.x == 0) {
        float S = 0.f, S2 = 0.f;
        #pragma unroll
        for (int w = 0; w < 8; w++) { S += ws[w]; S2 += ws2[w]; }
        float mean = S / (float)OUT_DIM;
        float var  = S2 / (float)OUT_DIM - mean * mean;
        sm_mean = mean; sm_rstd = rsqrtf(var + 1e-5f);
    }
    __syncthreads();
    float mean = sm_mean, rstd = sm_rstd;
    for (int o = threadIdx.x; o < OUT_DIM; o += blockDim.x) {
        float y = (kbuf[o] - mean) * rstd * ln_g[o] + ln_b[o];
        __nv_bfloat16 hi, lo; split2(y, hi, lo);
        kd[o] = hi;
        kd[OUT_DIM + o]     = isSup ? lo : hi;
        kd[2 * OUT_DIM + o] = isSup ? hi : lo;
    }
}

// ---------------------------------------------------------------------------
// per-row blockwise softmax; writes hi/lo A-layout attn directly to g_Ahl.
// 5 warps per block, warp w handles the 140-column segment of class w and
// writes rows of g_Ahl[w] (hi at 0 & 140, lo at 280, zeros at 420..447).
// ---------------------------------------------------------------------------
__global__ __launch_bounds__(160)
void softmax_kernel()
{
    int row = blockIdx.x;
    int warp = threadIdx.x >> 5, lane = threadIdx.x & 31;
    const float* p = g_S + (size_t)row * ROWS_S + warp * SEG;
    float v[5]; float mx = -INFINITY;
    #pragma unroll
    for (int i = 0; i < 5; i++) {
        int c = lane + 32 * i;
        v[i] = (c < SEG) ? p[c] : -INFINITY;
        mx = fmaxf(mx, v[i]);
    }
    #pragma unroll
    for (int off = 16; off; off >>= 1)
        mx = fmaxf(mx, __shfl_xor_sync(0xffffffffu, mx, off));
    float sm = 0.f;
    #pragma unroll
    for (int i = 0; i < 5; i++) {
        int c = lane + 32 * i;
        v[i] = (c < SEG) ? expf(v[i] - mx) : 0.f;
        sm += v[i];
    }
    #pragma unroll
    for (int off = 16; off; off >>= 1)
        sm += __shfl_xor_sync(0xffffffffu, sm, off);
    float inv = 1.f / sm;

    __nv_bfloat16* a = g_Ahl + ((size_t)warp * ROWS_Q + row) * KPR;
    #pragma unroll
    for (int i = 0; i < 5; i++) {
        int c = lane + 32 * i;
        if (c < SEG) {
            float x = v[i] * inv;
            __nv_bfloat16 hi, lo; split2(x, hi, lo);
            a[c] = hi;
            a[SEG + c] = hi;
            a[2 * SEG + c] = lo;
        }
    }
    if (lane < KPR - 3 * SEG)          // zero pad 420..447
        a[3 * SEG + lane] = __float2bfloat16(0.f);
}

// ---------------------------------------------------------------------------
// per-query Gram matrix + distances -> sim, ori
// ---------------------------------------------------------------------------
__global__ __launch_bounds__(256)
void finalize_kernel(float* __restrict__ out)
{
    int q = blockIdx.x;
    const float* v = g_vs_q + (size_t)q * PLANE;
    const float* pp[WAY];
    #pragma unroll
    for (int w = 0; w < WAY; w++)
        pp[w] = g_proto + (size_t)w * ROWS_Q * OUT_DIM + (size_t)q * PLANE;

    float acc[21];
    #pragma unroll
    for (int i = 0; i < 21; i++) acc[i] = 0.f;

    for (int i = threadIdx.x; i < PLANE; i += blockDim.x) {
        float vv = v[i];
        float a0 = pp[0][i], a1 = pp[1][i], a2 = pp[2][i], a3 = pp[3][i], a4 = pp[4][i];
        acc[0]  += a0 * a0;  acc[1]  += a0 * a1;  acc[2]  += a0 * a2;
        acc[3]  += a0 * a3;  acc[4]  += a0 * a4;
        acc[5]  += a1 * a1;  acc[6]  += a1 * a2;  acc[7]  += a1 * a3;  acc[8]  += a1 * a4;
        acc[9]  += a2 * a2;  acc[10] += a2 * a3;  acc[11] += a2 * a4;
        acc[12] += a3 * a3;  acc[13] += a3 * a4;
        acc[14] += a4 * a4;
        acc[15] += vv * a0;  acc[16] += vv * a1;  acc[17] += vv * a2;
        acc[18] += vv * a3;  acc[19] += vv * a4;
        acc[20] += vv * vv;
    }

    int lane = threadIdx.x & 31, wid = threadIdx.x >> 5;
    __shared__ float part[21][8];
    #pragma unroll
    for (int i = 0; i < 21; i++) {
        float a = acc[i];
        #pragma unroll
        for (int off = 16; off; off >>= 1)
            a += __shfl_xor_sync(0xffffffffu, a, off);
        if (lane == 0) part[i][wid] = a;
    }
    __syncthreads();
    __shared__ float tot[21];
    if (threadIdx.x < 21) {
        float sSum = 0.f;
        #pragma unroll
        for (int w = 0; w < 8; w++) sSum += part[threadIdx.x][w];
        tot[threadIdx.x] = sSum;
    }
    __syncthreads();
    if (threadIdx.x == 0) {
        float G[WAY][WAY];
        int t = 0;
        for (int a = 0; a < WAY; a++)
            for (int b = a; b < WAY; b++) { G[a][b] = tot[t]; G[b][a] = tot[t]; t++; }
        float D[WAY];
        for (int w = 0; w < WAY; w++) D[w] = tot[15 + w];
        float VV = tot[20];
        float nrm[WAY];
        for (int w = 0; w < WAY; w++) nrm[w] = sqrtf(G[w][w]);
        for (int a = 0; a < WAY; a++)
            for (int b = 0; b < WAY; b++)
                out[q * WAY * WAY + a * WAY + b] =
                    G[a][b] / fmaxf(nrm[a] * nrm[b], 1e-8f);
        for (int w = 0; w < WAY; w++)
            out[N_QUERIES * WAY * WAY + q * WAY + w] =
                -(VV - 2.f * D[w] + G[w][w]) / (float)L_TUP;
    }
}

// ---------------------------------------------------------------------------
// Launch
// ---------------------------------------------------------------------------
extern "C" void kernel_launch(void* const* d_in, const int* in_sizes, int n_in,
                              void* d_out, int out_size)
{
    const float* support = (const float*)d_in[0];
    const float* queries = (const float*)d_in[2];
    const float* k_w  = (const float*)d_in[3];
    const float* k_b  = (const float*)d_in[4];
    const float* v_w  = (const float*)d_in[5];
    const float* v_b  = (const float*)d_in[6];
    const float* ln_g = (const float*)d_in[7];
    const float* ln_b = (const float*)d_in[8];
    float* out = (float*)d_out;

    float *P, *S, *proto;
    __nv_bfloat16 *Xhl, *Whl, *KQhl, *KShl, *Ahl, *Vhl;
    cudaGetSymbolAddress((void**)&Xhl,   g_Xhl);
    cudaGetSymbolAddress((void**)&Whl,   g_Whl);
    cudaGetSymbolAddress((void**)&P,     g_P);
    cudaGetSymbolAddress((void**)&KQhl,  g_KQhl);
    cudaGetSymbolAddress((void**)&KShl,  g_KShl);
    cudaGetSymbolAddress((void**)&S,     g_S);
    cudaGetSymbolAddress((void**)&Ahl,   g_Ahl);
    cudaGetSymbolAddress((void**)&Vhl,   g_Vhl);
    cudaGetSymbolAddress((void**)&proto, g_proto);

    // 1. fused PE + hi/lo conversion; weight conversion
    conv_pe_hilo<<<(ROWS_X * D_MODEL + 255) / 256, 256>>>(support, queries);
    convW_kernel<<<(NSTACK * D_MODEL + 255) / 256, 256>>>(k_w, v_w);
    // 2. P = X @ Wt^T  [1800, 4608], K=6144
    {
        dim3 grid(NSTACK / 128, (ROWS_X + 127) / 128, 1);
        gemm_mma<<<grid, 256>>>(Xhl, Whl, P, ROWS_X, NSTACK, KBIG, 1.0f, 0, 0, 0);
    }
    // 3. assemble -> KQhl/KShl (split bf16) + vs float
    assemble_kernel<<<N_TOTAL * L_TUP, 256>>>(k_b, v_b, ln_g, ln_b);
    // 4. scores = ks_q @ ks_s^T / sqrt(OUT_DIM)  [5600, 700], K=3456
    {
        dim3 grid((ROWS_S + 127) / 128, (ROWS_Q + 127) / 128, 1);
        gemm_mma<<<grid, 256>>>(KQhl, KShl, S, ROWS_Q, ROWS_S, KSC,
                                1.0f / sqrtf((float)OUT_DIM), 0, 0, 0);
    }
    // 5. softmax -> g_Ahl directly
    softmax_kernel<<<ROWS_Q, 160>>>();
    // 6. vs_s^T hi/lo for proto GEMM
    conv_vsT_kernel<<<(WAY * OUT_DIM * KPR + 255) / 256, 256>>>();
    // 7. proto[w] = attn_w @ vs_w  [5600, 1152], K=448 — batched over z
    {
        dim3 grid(OUT_DIM / 128, (ROWS_Q + 127) / 128, WAY);
        gemm_mma<<<grid, 256>>>(Ahl, Vhl, proto, ROWS_Q, OUT_DIM, KPR, 1.0f,
                                (size_t)ROWS_Q * KPR,
                                (size_t)OUT_DIM * KPR,
                                (size_t)ROWS_Q * OUT_DIM);
    }
    // 8. finalize
    finalize_kernel<<<N_QUERIES, 256>>>(out);
}